// round 1
// baseline (speedup 1.0000x reference)
#include <cuda_runtime.h>
#include <cstddef>

#define N_NODE 50000
#define N_EDGE 625000
#define FD 128
#define HID 128
#define IN_DIM 256
#define EPS 1e-5f
#define TM 128

// scratch: aggregated edge features per node
__device__ float g_agg[(size_t)N_NODE * FD];

// ---------------------------------------------------------------------------
// Kernel 1: zero the aggregation buffer (graph replays => must re-zero)
// ---------------------------------------------------------------------------
__global__ void zero_agg_kernel() {
    int i = blockIdx.x * blockDim.x + threadIdx.x;
    if (i < N_NODE * FD / 4) {
        ((float4*)g_agg)[i] = make_float4(0.f, 0.f, 0.f, 0.f);
    }
}

// ---------------------------------------------------------------------------
// Kernel 2: scatter-add edge features into g_agg[receiver].
// One warp per edge; each lane handles 4 floats via red.global.add.v4.f32.
// ---------------------------------------------------------------------------
__global__ void scatter_edges_kernel(const int* __restrict__ em,
                                     const float* __restrict__ ef) {
    int e = blockIdx.x * 8 + (threadIdx.x >> 5);
    if (e >= N_EDGE) return;
    int lane = threadIdx.x & 31;
    int r = em[N_EDGE + e];  // row 1 of [2, N_EDGE] = receiver idx
    float4 v = *(const float4*)(ef + (size_t)e * FD + lane * 4);
    float* dst = g_agg + (size_t)r * FD + lane * 4;
    asm volatile("red.global.add.v4.f32 [%0], {%1,%2,%3,%4};"
                 :: "l"(dst), "f"(v.x), "f"(v.y), "f"(v.z), "f"(v.w)
                 : "memory");
}

// ---------------------------------------------------------------------------
// Kernel 3: fused 3-layer MLP + LayerNorm + residual.
// Block = 256 threads processes TM=128 nodes. 16x16 thread grid, each thread
// computes an 8x8 microtile. Activations stay in SMEM between layers.
// ---------------------------------------------------------------------------
#define SROW_H 132  // hs col stride (pad 4)
#define SROW_X 36   // xs col stride (32 + pad 4)
#define SROW_W 132  // ws col stride (pad 4)
#define SMEM_FLOATS (TM * SROW_H + TM * SROW_X + 32 * SROW_W)
#define SMEM_BYTES (SMEM_FLOATS * 4)

__global__ void __launch_bounds__(256, 2)
mlp_ln_kernel(const float* __restrict__ nf,
              const float* __restrict__ W1, const float* __restrict__ b1,
              const float* __restrict__ W2, const float* __restrict__ b2,
              const float* __restrict__ W3, const float* __restrict__ b3,
              const float* __restrict__ gamma_p, const float* __restrict__ beta_p,
              float* __restrict__ out) {
    extern __shared__ float smem[];
    float* hs = smem;                     // [TM][SROW_H] activations
    float* xs = hs + TM * SROW_H;         // [TM][SROW_X] layer-1 input tile
    float* ws = xs + TM * SROW_X;         // [32][SROW_W] weight tile

    const int tid = threadIdx.x;
    const int tx = tid & 15;
    const int ty = tid >> 4;
    const int base = blockIdx.x * TM;

    float acc[8][8];
#pragma unroll
    for (int i = 0; i < 8; ++i)
#pragma unroll
        for (int j = 0; j < 8; ++j) acc[i][j] = 0.f;

    // ================= Layer 1: X[128 x 256] @ W1[256 x 128] =================
    for (int kt = 0; kt < 8; ++kt) {
        // stage X tile [128 rows][32 k] (concat: k<128 -> nf, else g_agg)
#pragma unroll
        for (int it = 0; it < 4; ++it) {
            int i = tid + it * 256;          // 1024 float4 slots
            int row = i >> 3, q = i & 7;
            int gk = kt * 32 + q * 4;
            float4 v = make_float4(0.f, 0.f, 0.f, 0.f);
            int node = base + row;
            if (node < N_NODE) {
                const float* src = (gk < FD)
                    ? (nf + (size_t)node * FD + gk)
                    : (g_agg + (size_t)node * FD + (gk - FD));
                v = *(const float4*)src;
            }
            *(float4*)(xs + row * SROW_X + q * 4) = v;
        }
        // stage W1 tile [32][128]
#pragma unroll
        for (int it = 0; it < 4; ++it) {
            int i = tid + it * 256;
            int k = i >> 5, cq = i & 31;
            float4 w = *(const float4*)(W1 + (size_t)(kt * 32 + k) * HID + cq * 4);
            *(float4*)(ws + k * SROW_W + cq * 4) = w;
        }
        __syncthreads();
#pragma unroll
        for (int k = 0; k < 32; ++k) {
            float a[8], b[8];
#pragma unroll
            for (int i = 0; i < 8; ++i) a[i] = xs[(ty * 8 + i) * SROW_X + k];
            float4 bv0 = *(float4*)(ws + k * SROW_W + tx * 8);
            float4 bv1 = *(float4*)(ws + k * SROW_W + tx * 8 + 4);
            b[0] = bv0.x; b[1] = bv0.y; b[2] = bv0.z; b[3] = bv0.w;
            b[4] = bv1.x; b[5] = bv1.y; b[6] = bv1.z; b[7] = bv1.w;
#pragma unroll
            for (int i = 0; i < 8; ++i)
#pragma unroll
                for (int j = 0; j < 8; ++j) acc[i][j] = fmaf(a[i], b[j], acc[i][j]);
        }
        __syncthreads();
    }
    // bias + relu -> hs
    {
        float4 bb0 = *(const float4*)(b1 + tx * 8);
        float4 bb1 = *(const float4*)(b1 + tx * 8 + 4);
        float bb[8] = {bb0.x, bb0.y, bb0.z, bb0.w, bb1.x, bb1.y, bb1.z, bb1.w};
#pragma unroll
        for (int i = 0; i < 8; ++i) {
            float4 v0, v1;
            v0.x = fmaxf(acc[i][0] + bb[0], 0.f);
            v0.y = fmaxf(acc[i][1] + bb[1], 0.f);
            v0.z = fmaxf(acc[i][2] + bb[2], 0.f);
            v0.w = fmaxf(acc[i][3] + bb[3], 0.f);
            v1.x = fmaxf(acc[i][4] + bb[4], 0.f);
            v1.y = fmaxf(acc[i][5] + bb[5], 0.f);
            v1.z = fmaxf(acc[i][6] + bb[6], 0.f);
            v1.w = fmaxf(acc[i][7] + bb[7], 0.f);
            *(float4*)(hs + (ty * 8 + i) * SROW_H + tx * 8) = v0;
            *(float4*)(hs + (ty * 8 + i) * SROW_H + tx * 8 + 4) = v1;
        }
    }
    __syncthreads();

    // ============== Layers 2 and 3: hs[128 x 128] @ W[128 x 128] ==============
    for (int layer = 0; layer < 2; ++layer) {
        const float* W = (layer == 0) ? W2 : W3;
        const float* bias = (layer == 0) ? b2 : b3;
#pragma unroll
        for (int i = 0; i < 8; ++i)
#pragma unroll
            for (int j = 0; j < 8; ++j) acc[i][j] = 0.f;

        for (int kt = 0; kt < 4; ++kt) {
#pragma unroll
            for (int it = 0; it < 4; ++it) {
                int i = tid + it * 256;
                int k = i >> 5, cq = i & 31;
                float4 w = *(const float4*)(W + (size_t)(kt * 32 + k) * HID + cq * 4);
                *(float4*)(ws + k * SROW_W + cq * 4) = w;
            }
            __syncthreads();
#pragma unroll
            for (int k = 0; k < 32; ++k) {
                int gk = kt * 32 + k;
                float a[8], b[8];
#pragma unroll
                for (int i = 0; i < 8; ++i) a[i] = hs[(ty * 8 + i) * SROW_H + gk];
                float4 bv0 = *(float4*)(ws + k * SROW_W + tx * 8);
                float4 bv1 = *(float4*)(ws + k * SROW_W + tx * 8 + 4);
                b[0] = bv0.x; b[1] = bv0.y; b[2] = bv0.z; b[3] = bv0.w;
                b[4] = bv1.x; b[5] = bv1.y; b[6] = bv1.z; b[7] = bv1.w;
#pragma unroll
                for (int i = 0; i < 8; ++i)
#pragma unroll
                    for (int j = 0; j < 8; ++j) acc[i][j] = fmaf(a[i], b[j], acc[i][j]);
            }
            __syncthreads();  // also protects hs before overwrite below
        }
        // bias (+relu for layer 2 only) -> hs
        {
            float4 bb0 = *(const float4*)(bias + tx * 8);
            float4 bb1 = *(const float4*)(bias + tx * 8 + 4);
            float bb[8] = {bb0.x, bb0.y, bb0.z, bb0.w, bb1.x, bb1.y, bb1.z, bb1.w};
            bool do_relu = (layer == 0);
#pragma unroll
            for (int i = 0; i < 8; ++i) {
                float v[8];
#pragma unroll
                for (int j = 0; j < 8; ++j) {
                    float t = acc[i][j] + bb[j];
                    v[j] = do_relu ? fmaxf(t, 0.f) : t;
                }
                *(float4*)(hs + (ty * 8 + i) * SROW_H + tx * 8) =
                    make_float4(v[0], v[1], v[2], v[3]);
                *(float4*)(hs + (ty * 8 + i) * SROW_H + tx * 8 + 4) =
                    make_float4(v[4], v[5], v[6], v[7]);
            }
        }
        __syncthreads();
    }

    // ================= LayerNorm + gamma/beta + residual =================
    {
        int lane = tid & 31;
        int wid = tid >> 5;  // 8 warps
        float4 g4 = *(const float4*)(gamma_p + lane * 4);
        float4 bt4 = *(const float4*)(beta_p + lane * 4);
        for (int r = wid; r < TM; r += 8) {
            int node = base + r;
            float4 h = *(float4*)(hs + r * SROW_H + lane * 4);
            float s = h.x + h.y + h.z + h.w;
            float sq = h.x * h.x + h.y * h.y + h.z * h.z + h.w * h.w;
#pragma unroll
            for (int o = 16; o > 0; o >>= 1) {
                s += __shfl_xor_sync(0xFFFFFFFFu, s, o);
                sq += __shfl_xor_sync(0xFFFFFFFFu, sq, o);
            }
            float mu = s * (1.f / 128.f);
            float var = sq * (1.f / 128.f) - mu * mu;
            float rinv = rsqrtf(var + EPS);
            if (node < N_NODE) {
                float4 nfv = *(const float4*)(nf + (size_t)node * FD + lane * 4);
                float4 o4;
                o4.x = (h.x - mu) * rinv * g4.x + bt4.x + nfv.x;
                o4.y = (h.y - mu) * rinv * g4.y + bt4.y + nfv.y;
                o4.z = (h.z - mu) * rinv * g4.z + bt4.z + nfv.z;
                o4.w = (h.w - mu) * rinv * g4.w + bt4.w + nfv.w;
                *(float4*)(out + (size_t)node * FD + lane * 4) = o4;
            }
        }
    }
}

// ---------------------------------------------------------------------------
extern "C" void kernel_launch(void* const* d_in, const int* in_sizes, int n_in,
                              void* d_out, int out_size) {
    const float* node_feature = (const float*)d_in[0];
    const int* edge_matrix    = (const int*)d_in[1];
    const float* edge_feature = (const float*)d_in[2];
    const float* W1 = (const float*)d_in[3];
    const float* b1 = (const float*)d_in[4];
    const float* W2 = (const float*)d_in[5];
    const float* b2 = (const float*)d_in[6];
    const float* W3 = (const float*)d_in[7];
    const float* b3 = (const float*)d_in[8];
    const float* gamma = (const float*)d_in[9];
    const float* beta  = (const float*)d_in[10];
    float* out = (float*)d_out;

    // 1) zero agg buffer
    int zn = N_NODE * FD / 4;
    zero_agg_kernel<<<(zn + 255) / 256, 256>>>();

    // 2) scatter-add edges (warp/edge)
    scatter_edges_kernel<<<(N_EDGE + 7) / 8, 256>>>(edge_matrix, edge_feature);

    // 3) fused MLP + LN + residual
    cudaFuncSetAttribute(mlp_ln_kernel,
                         cudaFuncAttributeMaxDynamicSharedMemorySize, SMEM_BYTES);
    int grid = (N_NODE + TM - 1) / TM;
    mlp_ln_kernel<<<grid, 256, SMEM_BYTES>>>(node_feature, W1, b1, W2, b2,
                                             W3, b3, gamma, beta, out);
}

// round 3
// speedup vs baseline: 1.7020x; 1.7020x over previous
#include <cuda_runtime.h>
#include <cstdint>
#include <cstddef>

#define N_NODE 50000
#define N_EDGE 625000
#define FD 128
#define HID 128
#define EPS 1e-5f
#define TM 128

// ---------------------------------------------------------------------------
// Device scratch (no allocs allowed)
// ---------------------------------------------------------------------------
__device__ float g_agg[(size_t)N_NODE * FD];
__device__ float g_Wt1[128 * 256];  // Wt1[n][k] = tf32(W1[k][n])
__device__ float g_Wt2[128 * 128];
__device__ float g_Wt3[128 * 128];

__device__ __forceinline__ float to_tf32(float x) {
    uint32_t r;
    asm("cvt.rna.tf32.f32 %0, %1;" : "=r"(r) : "f"(x));
    return __uint_as_float(r);
}

// ---------------------------------------------------------------------------
// Kernel 1: zero the aggregation buffer
// ---------------------------------------------------------------------------
__global__ void zero_agg_kernel() {
    int i = blockIdx.x * blockDim.x + threadIdx.x;
    if (i < N_NODE * FD / 4)
        ((float4*)g_agg)[i] = make_float4(0.f, 0.f, 0.f, 0.f);
}

// ---------------------------------------------------------------------------
// Kernel 2: scatter-add edge features (warp/edge, red.global.add.v4)
// ---------------------------------------------------------------------------
__global__ void scatter_edges_kernel(const int* __restrict__ em,
                                     const float* __restrict__ ef) {
    int e = blockIdx.x * 8 + (threadIdx.x >> 5);
    if (e >= N_EDGE) return;
    int lane = threadIdx.x & 31;
    int r = em[N_EDGE + e];
    float4 v = *(const float4*)(ef + (size_t)e * FD + lane * 4);
    float* dst = g_agg + (size_t)r * FD + lane * 4;
    asm volatile("red.global.add.v4.f32 [%0], {%1,%2,%3,%4};"
                 :: "l"(dst), "f"(v.x), "f"(v.y), "f"(v.z), "f"(v.w) : "memory");
}

// ---------------------------------------------------------------------------
// Kernel 3: transpose + tf32-round weights into n-major device globals
// ---------------------------------------------------------------------------
__global__ void prep_weights_kernel(const float* __restrict__ W1,
                                    const float* __restrict__ W2,
                                    const float* __restrict__ W3) {
    int i = blockIdx.x * blockDim.x + threadIdx.x;
    if (i < 256 * 128) {                  // W1 [256][128] -> Wt1[n][k]
        int k = i >> 7, n = i & 127;
        g_Wt1[n * 256 + k] = to_tf32(W1[i]);
    } else if (i < 256 * 128 + 128 * 128) {
        int j = i - 256 * 128;
        int k = j >> 7, n = j & 127;
        g_Wt2[n * 128 + k] = to_tf32(W2[j]);
    } else if (i < 256 * 128 + 2 * 128 * 128) {
        int j = i - 256 * 128 - 128 * 128;
        int k = j >> 7, n = j & 127;
        g_Wt3[n * 128 + k] = to_tf32(W3[j]);
    }
}

// ---------------------------------------------------------------------------
// Kernel 4: fused tf32 mma.sync 3-layer MLP + LayerNorm + residual.
// 256 threads / 128 nodes per block. 8 warps, each owns a 16-row strip and
// computes 16 x (m16n8k8) tiles covering N=128 per k-step.
// SMEM strides 36 / 132 floats ( == 4 mod 32 ) make all fragment LDS
// conflict-free: bank = (4*grp + tig) mod 32, a lane permutation.
// ---------------------------------------------------------------------------
#define XS_STRIDE 36
#define WS_STRIDE 36
#define HS_STRIDE 132
#define SMEM_FLOATS (128 * HS_STRIDE + 128 * WS_STRIDE + 128 * XS_STRIDE + 5 * 128)
#define SMEM_BYTES (SMEM_FLOATS * 4)

#define MMA_TF32(c, a0, a1, a2, a3, b0, b1)                                       \
    asm volatile("mma.sync.aligned.m16n8k8.row.col.f32.tf32.tf32.f32 "            \
                 "{%0,%1,%2,%3}, {%4,%5,%6,%7}, {%8,%9}, {%0,%1,%2,%3};"          \
                 : "+f"((c)[0]), "+f"((c)[1]), "+f"((c)[2]), "+f"((c)[3])         \
                 : "r"(a0), "r"(a1), "r"(a2), "r"(a3), "r"(b0), "r"(b1))

__global__ void __launch_bounds__(256, 2)
mlp_mma_kernel(const float* __restrict__ nf,
               const float* __restrict__ b1, const float* __restrict__ b2,
               const float* __restrict__ b3, const float* __restrict__ gamma_p,
               const float* __restrict__ beta_p, float* __restrict__ out) {
    extern __shared__ float smem[];
    float* hs = smem;                        // [128][132] activations
    float* ws = hs + 128 * HS_STRIDE;        // [128 n][36] weight k-chunk
    float* xs = ws + 128 * WS_STRIDE;        // [128][36] layer-1 input k-chunk
    float* sBias = xs + 128 * XS_STRIDE;     // b1,b2,b3,gamma,beta

    const int tid = threadIdx.x;
    const int wid = tid >> 5;
    const int lid = tid & 31;
    const int grp = lid >> 2;    // 0..7 (row within half-strip)
    const int tig = lid & 3;     // 0..3
    const int r0 = wid * 16 + grp;   // first row this thread touches
    const int base = blockIdx.x * TM;

    if (tid < 128) {
        sBias[tid]       = b1[tid];
        sBias[128 + tid] = b2[tid];
        sBias[256 + tid] = b3[tid];
        sBias[384 + tid] = gamma_p[tid];
        sBias[512 + tid] = beta_p[tid];
    }

    float acc[16][4];
#pragma unroll
    for (int nt = 0; nt < 16; ++nt)
#pragma unroll
        for (int j = 0; j < 4; ++j) acc[nt][j] = 0.f;

    // ===================== Layer 1: X[128x256] @ W1 =====================
    for (int kt = 0; kt < 8; ++kt) {
#pragma unroll
        for (int it = 0; it < 4; ++it) {
            int i = tid + it * 256;          // 1024 float4 slots
            int row = i >> 3, q = i & 7;
            int gk = kt * 32 + q * 4;
            // X: concat(nf, agg), tf32-rounded
            float4 v = make_float4(0.f, 0.f, 0.f, 0.f);
            int node = base + row;
            if (node < N_NODE) {
                const float* src = (gk < FD)
                    ? nf + (size_t)node * FD + gk
                    : g_agg + (size_t)node * FD + (gk - FD);
                v = *(const float4*)src;
            }
            v.x = to_tf32(v.x); v.y = to_tf32(v.y);
            v.z = to_tf32(v.z); v.w = to_tf32(v.w);
            *(float4*)(xs + row * XS_STRIDE + q * 4) = v;
            // W: Wt1[n][k] chunk
            float4 w = *(const float4*)(g_Wt1 + (size_t)row * 256 + gk);
            *(float4*)(ws + row * WS_STRIDE + q * 4) = w;
        }
        __syncthreads();
#pragma unroll
        for (int ks = 0; ks < 4; ++ks) {
            int kb = ks * 8;
            uint32_t a0 = __float_as_uint(xs[r0 * XS_STRIDE + kb + tig]);
            uint32_t a1 = __float_as_uint(xs[(r0 + 8) * XS_STRIDE + kb + tig]);
            uint32_t a2 = __float_as_uint(xs[r0 * XS_STRIDE + kb + tig + 4]);
            uint32_t a3 = __float_as_uint(xs[(r0 + 8) * XS_STRIDE + kb + tig + 4]);
#pragma unroll
            for (int nt = 0; nt < 16; ++nt) {
                const float* wrow = ws + (nt * 8 + grp) * WS_STRIDE + kb + tig;
                uint32_t b0 = __float_as_uint(wrow[0]);
                uint32_t bb = __float_as_uint(wrow[4]);
                MMA_TF32(acc[nt], a0, a1, a2, a3, b0, bb);
            }
        }
        __syncthreads();
    }

    // epilogue 1: bias+relu -> tf32 -> hs
#pragma unroll
    for (int nt = 0; nt < 16; ++nt) {
        int col = nt * 8 + tig * 2;
        float2 v0, v1;
        v0.x = to_tf32(fmaxf(acc[nt][0] + sBias[col], 0.f));
        v0.y = to_tf32(fmaxf(acc[nt][1] + sBias[col + 1], 0.f));
        v1.x = to_tf32(fmaxf(acc[nt][2] + sBias[col], 0.f));
        v1.y = to_tf32(fmaxf(acc[nt][3] + sBias[col + 1], 0.f));
        *(float2*)(hs + r0 * HS_STRIDE + col) = v0;
        *(float2*)(hs + (r0 + 8) * HS_STRIDE + col) = v1;
    }
    __syncthreads();

    // ===================== Layers 2 and 3: H[128x128] @ W =====================
    for (int l = 0; l < 2; ++l) {
        const float* Wt = l ? g_Wt3 : g_Wt2;
#pragma unroll
        for (int nt = 0; nt < 16; ++nt)
#pragma unroll
            for (int j = 0; j < 4; ++j) acc[nt][j] = 0.f;

        for (int kt = 0; kt < 4; ++kt) {
#pragma unroll
            for (int it = 0; it < 4; ++it) {
                int i = tid + it * 256;
                int n = i >> 3, q = i & 7;
                float4 w = *(const float4*)(Wt + (size_t)n * 128 + kt * 32 + q * 4);
                *(float4*)(ws + n * WS_STRIDE + q * 4) = w;
            }
            __syncthreads();
#pragma unroll
            for (int ks = 0; ks < 4; ++ks) {
                int gk = kt * 32 + ks * 8;
                int kb = ks * 8;
                uint32_t a0 = __float_as_uint(hs[r0 * HS_STRIDE + gk + tig]);
                uint32_t a1 = __float_as_uint(hs[(r0 + 8) * HS_STRIDE + gk + tig]);
                uint32_t a2 = __float_as_uint(hs[r0 * HS_STRIDE + gk + tig + 4]);
                uint32_t a3 = __float_as_uint(hs[(r0 + 8) * HS_STRIDE + gk + tig + 4]);
#pragma unroll
                for (int nt = 0; nt < 16; ++nt) {
                    const float* wrow = ws + (nt * 8 + grp) * WS_STRIDE + kb + tig;
                    uint32_t b0 = __float_as_uint(wrow[0]);
                    uint32_t bb = __float_as_uint(wrow[4]);
                    MMA_TF32(acc[nt], a0, a1, a2, a3, b0, bb);
                }
            }
            __syncthreads();
        }

        if (l == 0) {
            // epilogue 2: bias+relu -> tf32 -> hs (own strip only; safe)
#pragma unroll
            for (int nt = 0; nt < 16; ++nt) {
                int col = nt * 8 + tig * 2;
                float2 v0, v1;
                v0.x = to_tf32(fmaxf(acc[nt][0] + sBias[128 + col], 0.f));
                v0.y = to_tf32(fmaxf(acc[nt][1] + sBias[128 + col + 1], 0.f));
                v1.x = to_tf32(fmaxf(acc[nt][2] + sBias[128 + col], 0.f));
                v1.y = to_tf32(fmaxf(acc[nt][3] + sBias[128 + col + 1], 0.f));
                *(float2*)(hs + r0 * HS_STRIDE + col) = v0;
                *(float2*)(hs + (r0 + 8) * HS_STRIDE + col) = v1;
            }
            __syncthreads();
        }
    }

    // ============= Final epilogue: +b3, LayerNorm, gamma/beta, residual =======
    {
        // add b3 in place; accumulate row sums
        float s0 = 0.f, sq0 = 0.f, s1 = 0.f, sq1 = 0.f;
#pragma unroll
        for (int nt = 0; nt < 16; ++nt) {
            int col = nt * 8 + tig * 2;
            acc[nt][0] += sBias[256 + col];
            acc[nt][1] += sBias[256 + col + 1];
            acc[nt][2] += sBias[256 + col];
            acc[nt][3] += sBias[256 + col + 1];
            s0 += acc[nt][0] + acc[nt][1];
            sq0 += acc[nt][0] * acc[nt][0] + acc[nt][1] * acc[nt][1];
            s1 += acc[nt][2] + acc[nt][3];
            sq1 += acc[nt][2] * acc[nt][2] + acc[nt][3] * acc[nt][3];
        }
        // reduce over the 4-lane quad (same rows)
#pragma unroll
        for (int o = 1; o <= 2; o <<= 1) {
            s0 += __shfl_xor_sync(0xFFFFFFFFu, s0, o);
            sq0 += __shfl_xor_sync(0xFFFFFFFFu, sq0, o);
            s1 += __shfl_xor_sync(0xFFFFFFFFu, s1, o);
            sq1 += __shfl_xor_sync(0xFFFFFFFFu, sq1, o);
        }
        float mu0 = s0 * (1.f / 128.f);
        float var0 = sq0 * (1.f / 128.f) - mu0 * mu0;
        float ri0 = rsqrtf(var0 + EPS);
        float mu1 = s1 * (1.f / 128.f);
        float var1 = sq1 * (1.f / 128.f) - mu1 * mu1;
        float ri1 = rsqrtf(var1 + EPS);

        int node0 = base + r0;
        int node1 = base + r0 + 8;
#pragma unroll
        for (int nt = 0; nt < 16; ++nt) {
            int col = nt * 8 + tig * 2;
            float g0 = sBias[384 + col], g1 = sBias[384 + col + 1];
            float be0 = sBias[512 + col], be1 = sBias[512 + col + 1];
            if (node0 < N_NODE) {
                float2 nv = *(const float2*)(nf + (size_t)node0 * FD + col);
                float2 o;
                o.x = (acc[nt][0] - mu0) * ri0 * g0 + be0 + nv.x;
                o.y = (acc[nt][1] - mu0) * ri0 * g1 + be1 + nv.y;
                *(float2*)(out + (size_t)node0 * FD + col) = o;
            }
            if (node1 < N_NODE) {
                float2 nv = *(const float2*)(nf + (size_t)node1 * FD + col);
                float2 o;
                o.x = (acc[nt][2] - mu1) * ri1 * g0 + be0 + nv.x;
                o.y = (acc[nt][3] - mu1) * ri1 * g1 + be1 + nv.y;
                *(float2*)(out + (size_t)node1 * FD + col) = o;
            }
        }
    }
}

// ---------------------------------------------------------------------------
extern "C" void kernel_launch(void* const* d_in, const int* in_sizes, int n_in,
                              void* d_out, int out_size) {
    const float* node_feature = (const float*)d_in[0];
    const int* edge_matrix    = (const int*)d_in[1];
    const float* edge_feature = (const float*)d_in[2];
    const float* W1 = (const float*)d_in[3];
    const float* b1 = (const float*)d_in[4];
    const float* W2 = (const float*)d_in[5];
    const float* b2 = (const float*)d_in[6];
    const float* W3 = (const float*)d_in[7];
    const float* b3 = (const float*)d_in[8];
    const float* gamma = (const float*)d_in[9];
    const float* beta  = (const float*)d_in[10];
    float* out = (float*)d_out;

    int zn = N_NODE * FD / 4;
    zero_agg_kernel<<<(zn + 255) / 256, 256>>>();

    prep_weights_kernel<<<(256 * 128 + 2 * 128 * 128 + 255) / 256, 256>>>(W1, W2, W3);

    scatter_edges_kernel<<<(N_EDGE + 7) / 8, 256>>>(edge_matrix, edge_feature);

    static int smem_set = 0;
    if (!smem_set) {
        cudaFuncSetAttribute(mlp_mma_kernel,
                             cudaFuncAttributeMaxDynamicSharedMemorySize, SMEM_BYTES);
        smem_set = 1;
    }
    int grid = (N_NODE + TM - 1) / TM;
    mlp_mma_kernel<<<grid, 256, SMEM_BYTES>>>(node_feature, b1, b2, b3,
                                              gamma, beta, out);
}

// round 4
// speedup vs baseline: 1.7422x; 1.0236x over previous
#include <cuda_runtime.h>
#include <cstdint>
#include <cstddef>

#define N_NODE 50000
#define N_EDGE 625000
#define FD 128
#define HID 128
#define EPS 1e-5f
#define TM 128

// ---------------------------------------------------------------------------
// Device scratch (no allocs allowed)
// ---------------------------------------------------------------------------
__device__ float g_agg[(size_t)N_NODE * FD];
__device__ float g_Wt1[128 * 256];  // Wt1[n][k] = tf32(W1[k][n])
__device__ float g_Wt2[128 * 128];
__device__ float g_Wt3[128 * 128];

__device__ __forceinline__ float to_tf32(float x) {
    uint32_t r;
    asm("cvt.rna.tf32.f32 %0, %1;" : "=r"(r) : "f"(x));
    return __uint_as_float(r);
}

__device__ __forceinline__ uint32_t smem_u32(const void* p) {
    uint32_t a;
    asm("{ .reg .u64 t; cvta.to.shared.u64 t, %1; cvt.u32.u64 %0, t; }"
        : "=r"(a) : "l"(p));
    return a;
}

// ldmatrix x4: four 8x8 b16 tiles (== four 8x4 f32 tiles for tf32 fragments)
__device__ __forceinline__ void ldsm4(uint32_t a[4], uint32_t addr) {
    asm volatile("ldmatrix.sync.aligned.m8n8.x4.shared.b16 {%0,%1,%2,%3}, [%4];"
                 : "=r"(a[0]), "=r"(a[1]), "=r"(a[2]), "=r"(a[3]) : "r"(addr));
}

// ---------------------------------------------------------------------------
// Kernel: scatter-add edge features (warp/edge, red.global.add.v4)
// ---------------------------------------------------------------------------
__global__ void scatter_edges_kernel(const int* __restrict__ em,
                                     const float* __restrict__ ef) {
    int e = blockIdx.x * 8 + (threadIdx.x >> 5);
    if (e >= N_EDGE) return;
    int lane = threadIdx.x & 31;
    int r = em[N_EDGE + e];
    float4 v = *(const float4*)(ef + (size_t)e * FD + lane * 4);
    float* dst = g_agg + (size_t)r * FD + lane * 4;
    asm volatile("red.global.add.v4.f32 [%0], {%1,%2,%3,%4};"
                 :: "l"(dst), "f"(v.x), "f"(v.y), "f"(v.z), "f"(v.w) : "memory");
}

// ---------------------------------------------------------------------------
// Kernel: transpose + tf32-round weights into n-major device globals
// ---------------------------------------------------------------------------
__global__ void prep_weights_kernel(const float* __restrict__ W1,
                                    const float* __restrict__ W2,
                                    const float* __restrict__ W3) {
    int i = blockIdx.x * blockDim.x + threadIdx.x;
    if (i < 256 * 128) {                  // W1 [256][128] -> Wt1[n][k]
        int k = i >> 7, n = i & 127;
        g_Wt1[n * 256 + k] = to_tf32(W1[i]);
    } else if (i < 256 * 128 + 128 * 128) {
        int j = i - 256 * 128;
        int k = j >> 7, n = j & 127;
        g_Wt2[n * 128 + k] = to_tf32(W2[j]);
    } else if (i < 256 * 128 + 2 * 128 * 128) {
        int j = i - 256 * 128 - 128 * 128;
        int k = j >> 7, n = j & 127;
        g_Wt3[n * 128 + k] = to_tf32(W3[j]);
    }
}

// ---------------------------------------------------------------------------
// Fused tf32 mma.sync MLP + LayerNorm + residual, ldmatrix fragment feed.
// 256 threads / 128 nodes. Warp w owns rows w*16..w*16+15, all 128 n-cols.
// Strides 36/132 ( == 4 mod 32 ) keep ldmatrix phases conflict-free.
// ---------------------------------------------------------------------------
#define XS_STRIDE 36
#define WS_STRIDE 36
#define HS_STRIDE 132
#define SMEM_FLOATS (128 * HS_STRIDE + 128 * WS_STRIDE + 128 * XS_STRIDE + 5 * 128)
#define SMEM_BYTES (SMEM_FLOATS * 4)

#define MMA_TF32(c, a0, a1, a2, a3, b0, b1)                                       \
    asm volatile("mma.sync.aligned.m16n8k8.row.col.f32.tf32.tf32.f32 "            \
                 "{%0,%1,%2,%3}, {%4,%5,%6,%7}, {%8,%9}, {%0,%1,%2,%3};"          \
                 : "+f"((c)[0]), "+f"((c)[1]), "+f"((c)[2]), "+f"((c)[3])         \
                 : "r"(a0), "r"(a1), "r"(a2), "r"(a3), "r"(b0), "r"(b1))

__global__ void __launch_bounds__(256, 2)
mlp_mma_kernel(const float* __restrict__ nf,
               const float* __restrict__ b1, const float* __restrict__ b2,
               const float* __restrict__ b3, const float* __restrict__ gamma_p,
               const float* __restrict__ beta_p, float* __restrict__ out) {
    extern __shared__ float smem[];
    float* hs = smem;                        // [128][132] activations
    float* ws = hs + 128 * HS_STRIDE;        // [128 n][36] weight k-chunk
    float* xs = ws + 128 * WS_STRIDE;        // [128][36] layer-1 input k-chunk
    float* sBias = xs + 128 * XS_STRIDE;     // b1,b2,b3,gamma,beta

    const int tid = threadIdx.x;
    const int wid = tid >> 5;
    const int lid = tid & 31;
    const int grp = lid >> 2;
    const int tig = lid & 3;
    const int r0 = wid * 16 + grp;
    const int base = blockIdx.x * TM;

    if (tid < 128) {
        sBias[tid]       = b1[tid];
        sBias[128 + tid] = b2[tid];
        sBias[256 + tid] = b3[tid];
        sBias[384 + tid] = gamma_p[tid];
        sBias[512 + tid] = beta_p[tid];
    }

    // per-lane ldmatrix address patterns
    // A tiles t0..t3 = (rows0-7,kb) (rows8-15,kb) (rows0-7,kb+4) (rows8-15,kb+4)
    const int a_row = (lid & 7) + ((lid >> 3) & 1) * 8;
    const int a_col = (lid >> 4) * 4;
    // B tiles t0..t3 = (n0-7,kb) (n0-7,kb+4) (n8-15,kb) (n8-15,kb+4)
    const int b_row = (lid & 7) + (lid >> 4) * 8;
    const int b_col = ((lid >> 3) & 1) * 4;

    const uint32_t aX = smem_u32(xs) + (uint32_t)(((wid * 16 + a_row) * XS_STRIDE + a_col) * 4);
    const uint32_t aH = smem_u32(hs) + (uint32_t)(((wid * 16 + a_row) * HS_STRIDE + a_col) * 4);
    const uint32_t bW = smem_u32(ws) + (uint32_t)((b_row * WS_STRIDE + b_col) * 4);

    float acc[16][4];
#pragma unroll
    for (int nt = 0; nt < 16; ++nt)
#pragma unroll
        for (int j = 0; j < 4; ++j) acc[nt][j] = 0.f;

    // ===================== Layer 1: X[128x256] @ W1 =====================
    for (int kt = 0; kt < 8; ++kt) {
#pragma unroll
        for (int it = 0; it < 4; ++it) {
            int i = tid + it * 256;          // 1024 float4 slots
            int row = i >> 3, q = i & 7;
            int gk = kt * 32 + q * 4;
            float4 v = make_float4(0.f, 0.f, 0.f, 0.f);
            int node = base + row;
            if (node < N_NODE) {
                const float* src = (gk < FD)
                    ? nf + (size_t)node * FD + gk
                    : g_agg + (size_t)node * FD + (gk - FD);
                v = *(const float4*)src;
            }
            v.x = to_tf32(v.x); v.y = to_tf32(v.y);
            v.z = to_tf32(v.z); v.w = to_tf32(v.w);
            *(float4*)(xs + row * XS_STRIDE + q * 4) = v;
            float4 w = *(const float4*)(g_Wt1 + (size_t)row * 256 + gk);
            *(float4*)(ws + row * WS_STRIDE + q * 4) = w;
        }
        __syncthreads();
#pragma unroll
        for (int ks = 0; ks < 4; ++ks) {
            uint32_t a[4];
            ldsm4(a, aX + (uint32_t)(ks * 8 * 4));
#pragma unroll
            for (int nt2 = 0; nt2 < 8; ++nt2) {
                uint32_t b[4];
                ldsm4(b, bW + (uint32_t)((nt2 * 16 * WS_STRIDE + ks * 8) * 4));
                MMA_TF32(acc[nt2 * 2],     a[0], a[1], a[2], a[3], b[0], b[1]);
                MMA_TF32(acc[nt2 * 2 + 1], a[0], a[1], a[2], a[3], b[2], b[3]);
            }
        }
        __syncthreads();
    }

    // epilogue 1: bias+relu -> tf32 -> hs
#pragma unroll
    for (int nt = 0; nt < 16; ++nt) {
        int col = nt * 8 + tig * 2;
        float2 v0, v1;
        v0.x = to_tf32(fmaxf(acc[nt][0] + sBias[col], 0.f));
        v0.y = to_tf32(fmaxf(acc[nt][1] + sBias[col + 1], 0.f));
        v1.x = to_tf32(fmaxf(acc[nt][2] + sBias[col], 0.f));
        v1.y = to_tf32(fmaxf(acc[nt][3] + sBias[col + 1], 0.f));
        *(float2*)(hs + r0 * HS_STRIDE + col) = v0;
        *(float2*)(hs + (r0 + 8) * HS_STRIDE + col) = v1;
    }
    __syncthreads();

    // ===================== Layers 2 and 3: H[128x128] @ W =====================
    for (int l = 0; l < 2; ++l) {
        const float* Wt = l ? g_Wt3 : g_Wt2;
#pragma unroll
        for (int nt = 0; nt < 16; ++nt)
#pragma unroll
            for (int j = 0; j < 4; ++j) acc[nt][j] = 0.f;

        for (int kt = 0; kt < 4; ++kt) {
#pragma unroll
            for (int it = 0; it < 4; ++it) {
                int i = tid + it * 256;
                int n = i >> 3, q = i & 7;
                float4 w = *(const float4*)(Wt + (size_t)n * 128 + kt * 32 + q * 4);
                *(float4*)(ws + n * WS_STRIDE + q * 4) = w;
            }
            __syncthreads();
#pragma unroll
            for (int ks = 0; ks < 4; ++ks) {
                uint32_t a[4];
                ldsm4(a, aH + (uint32_t)((kt * 32 + ks * 8) * 4));
#pragma unroll
                for (int nt2 = 0; nt2 < 8; ++nt2) {
                    uint32_t b[4];
                    ldsm4(b, bW + (uint32_t)((nt2 * 16 * WS_STRIDE + ks * 8) * 4));
                    MMA_TF32(acc[nt2 * 2],     a[0], a[1], a[2], a[3], b[0], b[1]);
                    MMA_TF32(acc[nt2 * 2 + 1], a[0], a[1], a[2], a[3], b[2], b[3]);
                }
            }
            __syncthreads();
        }

        if (l == 0) {
#pragma unroll
            for (int nt = 0; nt < 16; ++nt) {
                int col = nt * 8 + tig * 2;
                float2 v0, v1;
                v0.x = to_tf32(fmaxf(acc[nt][0] + sBias[128 + col], 0.f));
                v0.y = to_tf32(fmaxf(acc[nt][1] + sBias[128 + col + 1], 0.f));
                v1.x = to_tf32(fmaxf(acc[nt][2] + sBias[128 + col], 0.f));
                v1.y = to_tf32(fmaxf(acc[nt][3] + sBias[128 + col + 1], 0.f));
                *(float2*)(hs + r0 * HS_STRIDE + col) = v0;
                *(float2*)(hs + (r0 + 8) * HS_STRIDE + col) = v1;
            }
            __syncthreads();
        }
    }

    // ============= Final epilogue: +b3, LayerNorm, gamma/beta, residual =======
    {
        float s0 = 0.f, sq0 = 0.f, s1 = 0.f, sq1 = 0.f;
#pragma unroll
        for (int nt = 0; nt < 16; ++nt) {
            int col = nt * 8 + tig * 2;
            acc[nt][0] += sBias[256 + col];
            acc[nt][1] += sBias[256 + col + 1];
            acc[nt][2] += sBias[256 + col];
            acc[nt][3] += sBias[256 + col + 1];
            s0 += acc[nt][0] + acc[nt][1];
            sq0 += acc[nt][0] * acc[nt][0] + acc[nt][1] * acc[nt][1];
            s1 += acc[nt][2] + acc[nt][3];
            sq1 += acc[nt][2] * acc[nt][2] + acc[nt][3] * acc[nt][3];
        }
#pragma unroll
        for (int o = 1; o <= 2; o <<= 1) {
            s0 += __shfl_xor_sync(0xFFFFFFFFu, s0, o);
            sq0 += __shfl_xor_sync(0xFFFFFFFFu, sq0, o);
            s1 += __shfl_xor_sync(0xFFFFFFFFu, s1, o);
            sq1 += __shfl_xor_sync(0xFFFFFFFFu, sq1, o);
        }
        float mu0 = s0 * (1.f / 128.f);
        float ri0 = rsqrtf(sq0 * (1.f / 128.f) - mu0 * mu0 + EPS);
        float mu1 = s1 * (1.f / 128.f);
        float ri1 = rsqrtf(sq1 * (1.f / 128.f) - mu1 * mu1 + EPS);

        int node0 = base + r0;
        int node1 = base + r0 + 8;
#pragma unroll
        for (int nt = 0; nt < 16; ++nt) {
            int col = nt * 8 + tig * 2;
            float g0 = sBias[384 + col], g1 = sBias[384 + col + 1];
            float be0 = sBias[512 + col], be1 = sBias[512 + col + 1];
            if (node0 < N_NODE) {
                float2 nv = *(const float2*)(nf + (size_t)node0 * FD + col);
                float2 o;
                o.x = (acc[nt][0] - mu0) * ri0 * g0 + be0 + nv.x;
                o.y = (acc[nt][1] - mu0) * ri0 * g1 + be1 + nv.y;
                *(float2*)(out + (size_t)node0 * FD + col) = o;
            }
            if (node1 < N_NODE) {
                float2 nv = *(const float2*)(nf + (size_t)node1 * FD + col);
                float2 o;
                o.x = (acc[nt][2] - mu1) * ri1 * g0 + be0 + nv.x;
                o.y = (acc[nt][3] - mu1) * ri1 * g1 + be1 + nv.y;
                *(float2*)(out + (size_t)node1 * FD + col) = o;
            }
        }
    }
}

// ---------------------------------------------------------------------------
extern "C" void kernel_launch(void* const* d_in, const int* in_sizes, int n_in,
                              void* d_out, int out_size) {
    const float* node_feature = (const float*)d_in[0];
    const int* edge_matrix    = (const int*)d_in[1];
    const float* edge_feature = (const float*)d_in[2];
    const float* W1 = (const float*)d_in[3];
    const float* b1 = (const float*)d_in[4];
    const float* W2 = (const float*)d_in[5];
    const float* b2 = (const float*)d_in[6];
    const float* W3 = (const float*)d_in[7];
    const float* b3 = (const float*)d_in[8];
    const float* gamma = (const float*)d_in[9];
    const float* beta  = (const float*)d_in[10];
    float* out = (float*)d_out;

    static void* agg_ptr = nullptr;
    static int inited = 0;
    if (!inited) {
        cudaGetSymbolAddress(&agg_ptr, g_agg);
        cudaFuncSetAttribute(mlp_mma_kernel,
                             cudaFuncAttributeMaxDynamicSharedMemorySize, SMEM_BYTES);
        inited = 1;
    }

    // 1) zero agg via DMA memset (graph memset node)
    cudaMemsetAsync(agg_ptr, 0, (size_t)N_NODE * FD * sizeof(float));

    // 2) weight prep (independent of scatter)
    prep_weights_kernel<<<(256 * 128 + 2 * 128 * 128 + 255) / 256, 256>>>(W1, W2, W3);

    // 3) scatter-add edges
    scatter_edges_kernel<<<(N_EDGE + 7) / 8, 256>>>(edge_matrix, edge_feature);

    // 4) fused MLP + LN + residual
    int grid = (N_NODE + TM - 1) / TM;
    mlp_mma_kernel<<<grid, 256, SMEM_BYTES>>>(node_feature, b1, b2, b3,
                                              gamma, beta, out);
}